// round 15
// baseline (speedup 1.0000x reference)
#include <cuda_runtime.h>
#include <cuda_fp16.h>
#include <cstdint>

// ---------------- problem dims ----------------
#define B_DIM 512
#define NIN   64
#define DIN   128
#define NOUT  64
#define DOUT  128
#define KSEL  4
#define YCOLS (NOUT * DOUT)        // 8192
#define BN_EPS 1e-5f

#define KD      (KSEL * DIN)       // 512 (logical K per head)
#define NCHUNK  8                  // 4 k-sel x 2 half-DIN; 64 fp16 per chunk
#define NMT     4                  // M-tiles per head (partial-stats slots)
#define NCTA    256                // all co-resident: 2/SM x 148 SMs = 296 slots

// ---------------- scratch (device globals; no allocation allowed) ----------------
__device__ __align__(16) __half  g_xh[B_DIM * NIN * DIN];     // 8.4 MB
__device__ __align__(16) __half  g_wt[NOUT * DOUT * KD];      // [o][e][k*128+d], 8.4 MB
__device__ __align__(16) float   g_psum[NMT * YCOLS];         // 128 KB
__device__ __align__(16) float   g_psq [NMT * YCOLS];         // 128 KB
__device__ unsigned int          g_bar[4];                    // monotonic ticket barriers

// ---------------- helpers ----------------
__device__ __forceinline__ uint32_t smem_u32(const void* p) {
    uint32_t a;
    asm("{ .reg .u64 t; cvta.to.shared.u64 t, %1; cvt.u32.u64 %0, t; }" : "=r"(a) : "l"(p));
    return a;
}
__device__ __forceinline__ void cp_async16(uint32_t dst, const void* src) {
    asm volatile("cp.async.cg.shared.global [%0], [%1], 16;" :: "r"(dst), "l"(src) : "memory");
}
__device__ __forceinline__ void cp_commit() {
    asm volatile("cp.async.commit_group;" ::: "memory");
}
template <int N>
__device__ __forceinline__ void cp_wait() {
    asm volatile("cp.async.wait_group %0;" :: "n"(N) : "memory");
}
__device__ __forceinline__ void ldsm_x4(uint32_t* r, uint32_t addr) {
    asm volatile("ldmatrix.sync.aligned.m8n8.x4.shared.b16 {%0,%1,%2,%3}, [%4];"
                 : "=r"(r[0]), "=r"(r[1]), "=r"(r[2]), "=r"(r[3]) : "r"(addr));
}
__device__ __forceinline__ void mma16816(float* d, const uint32_t* a, uint32_t b0, uint32_t b1) {
    asm volatile(
        "mma.sync.aligned.m16n8k16.row.col.f32.f16.f16.f32 "
        "{%0,%1,%2,%3}, {%4,%5,%6,%7}, {%8,%9}, {%0,%1,%2,%3};"
        : "+f"(d[0]), "+f"(d[1]), "+f"(d[2]), "+f"(d[3])
        : "r"(a[0]), "r"(a[1]), "r"(a[2]), "r"(a[3]), "r"(b0), "r"(b1));
}
__device__ __forceinline__ float rcp_fast(float x) {
    float r;
    asm("rcp.approx.f32 %0, %1;" : "=f"(r) : "f"(x));
    return r;
}
__device__ __forceinline__ void stg_cs_f2(float* p, float2 v) {
    asm volatile("st.global.cs.v2.f32 [%0], {%1, %2};" :: "l"(p), "f"(v.x), "f"(v.y) : "memory");
}

// Grid-wide barrier: monotonic ticket counter, no reset needed (replay-safe).
__device__ __forceinline__ void grid_barrier(int slot) {
    __syncthreads();
    if (threadIdx.x == 0) {
        __threadfence();
        unsigned ticket = atomicAdd(&g_bar[slot], 1u);
        unsigned target = (ticket / NCTA + 1u) * NCTA;
        unsigned v;
        do {
            asm volatile("ld.acquire.gpu.u32 %0, [%1];"
                         : "=r"(v) : "l"(&g_bar[slot]));
        } while ((int)(v - target) < 0);
    }
    __syncthreads();
}

// ---------------- THE mega kernel ----------------
#define STAGE_BYTES 32768
#define GEMM_SMEM_BYTES (3 * STAGE_BYTES + 1024)

__global__ void __launch_bounds__(256, 2)
eb_mega(const float* __restrict__ x, const float* __restrict__ W,
        const float* __restrict__ gamma, const float* __restrict__ beta,
        const int* __restrict__ idx, float* __restrict__ out) {
    extern __shared__ char dsm[];
    uint32_t raw = smem_u32(dsm);
    uint32_t sbase = (raw + 1023u) & ~1023u;
    char* sptr = dsm + (sbase - raw);

    const int tid  = threadIdx.x;
    const int bid  = blockIdx.x;

    // ================= phase 0: convert inputs =================
    {
        const float4* xin = reinterpret_cast<const float4*>(x);
        #pragma unroll
        for (int it = 0; it < 16; ++it) {
            int i = bid * 4096 + it * 256 + tid;
            float4 v = xin[i];
            __half2 p0 = __floats2half2_rn(v.x, v.y);
            __half2 p1 = __floats2half2_rn(v.z, v.w);
            uint2 pk;
            pk.x = *reinterpret_cast<uint32_t*>(&p0);
            pk.y = *reinterpret_cast<uint32_t*>(&p1);
            reinterpret_cast<uint2*>(g_xh)[i] = pk;
        }
        float* tile = reinterpret_cast<float*>(sptr);   // [128][33]
        int o = bid >> 2, k = bid & 3;
        const float4* src4 = reinterpret_cast<const float4*>(W + (size_t)bid * (DIN * DOUT));
        for (int eb = 0; eb < 4; ++eb) {
            __syncthreads();
            #pragma unroll
            for (int it = 0; it < 4; ++it) {
                int flat = it * 256 + tid;          // 0..1023
                int d = flat >> 3, e4 = flat & 7;
                float4 v = src4[d * (DOUT / 4) + eb * 8 + e4];
                float* trow = tile + d * 33 + e4 * 4;
                trow[0] = v.x; trow[1] = v.y; trow[2] = v.z; trow[3] = v.w;
            }
            __syncthreads();
            #pragma unroll
            for (int it = 0; it < 16; ++it) {
                int flat = it * 256 + tid;
                int e2 = flat >> 7, d = flat & 127;
                float v = tile[d * 33 + e2];
                size_t off = (size_t)o * (DOUT * KD) + (size_t)(eb * 32 + e2) * KD + k * DIN + d;
                g_wt[off] = __float2half_rn(v);
            }
        }
    }
    grid_barrier(0);

    // ================= phase 1: GEMM + stats (accumulators stay live) =================
    const int lane = tid & 31;
    const int wid  = tid >> 5;
    const int warp_m = wid & 3;          // 4 M-warps of 32 rows
    const int warp_n = wid >> 2;         // 2 N-warps of 64 cols
    const int o  = bid >> 2;
    const int mt = bid & 3;

    float acc[2][8][4];
    #pragma unroll
    for (int mi = 0; mi < 2; ++mi)
        #pragma unroll
        for (int ni = 0; ni < 8; ++ni)
            #pragma unroll
            for (int q = 0; q < 4; ++q) acc[mi][ni][q] = 0.0f;

    {
        int nin[4];
        #pragma unroll
        for (int k = 0; k < 4; ++k) nin[k] = idx[(o << 2) + k];

        auto prefetch = [&](int c) {
            int k = c >> 1, dh = c & 1;
            uint32_t abuf = sbase + (uint32_t)(c % 3) * STAGE_BYTES;
            uint32_t bbuf = abuf + 16384;
            const __half* abase = g_xh + ((size_t)(mt * 128) * NIN + nin[k]) * DIN + dh * 64;
            const __half* bbase = g_wt + (size_t)o * (DOUT * KD) + k * DIN + dh * 64;
            #pragma unroll
            for (int it = 0; it < 4; ++it) {
                int v = it * 256 + tid;          // 1024 16B chunks per tile
                int row = v >> 3, cc = v & 7;
                uint32_t dsw = (uint32_t)row * 128 + (((uint32_t)cc * 16) ^ (((uint32_t)row & 7) << 4));
                cp_async16(abuf + dsw, abase + (size_t)row * (NIN * DIN) + cc * 8);
                cp_async16(bbuf + dsw, bbase + (size_t)row * KD + cc * 8);
            }
        };

        const int sub = lane >> 3;
        const int rowA = warp_m * 32 + (sub & 1) * 8 + (lane & 7);
        const int khA  = sub >> 1;
        const uint32_t swzA = ((uint32_t)rowA & 7) << 4;
        const int rowB = warp_n * 64 + (sub >> 1) * 8 + (lane & 7);
        const int khB  = sub & 1;
        const uint32_t swzB = ((uint32_t)rowB & 7) << 4;

        prefetch(0); cp_commit();
        prefetch(1); cp_commit();

        #pragma unroll
        for (int c = 0; c < NCHUNK; ++c) {       // fully unrolled: stage offsets immediate
            cp_wait<1>();
            __syncthreads();

            const uint32_t abuf = sbase + (uint32_t)(c % 3) * STAGE_BYTES;
            const uint32_t bbuf = abuf + 16384;
            const uint32_t aA  = abuf + (uint32_t)rowA * 128;
            const uint32_t aB  = bbuf + (uint32_t)rowB * 128;

            // first-ks fragment loads FIRST (data resident) — before the cp.async burst
            uint32_t b[2][4][4];
            uint32_t a0[2][4];
            {
                uint32_t kb0 = ((uint32_t)khB * 16) ^ swzB;
                uint32_t ka0 = ((uint32_t)khA * 16) ^ swzA;
                #pragma unroll
                for (int nb = 0; nb < 4; ++nb)
                    ldsm_x4(b[0][nb], aB + (uint32_t)(nb * 16) * 128 + kb0);
                ldsm_x4(a0[0], aA + ka0);
                ldsm_x4(a0[1], aA + 16 * 128 + ka0);
            }

            if (c + 2 < NCHUNK) prefetch(c + 2);
            cp_commit();

            #pragma unroll
            for (int ks = 0; ks < 4; ++ks) {
                const int cur = ks & 1;
                uint32_t a[2][4];
                if (ks == 0) {
                    #pragma unroll
                    for (int q = 0; q < 4; ++q) { a[0][q] = a0[0][q]; a[1][q] = a0[1][q]; }
                } else {
                    uint32_t ka = (((uint32_t)ks * 32 + (uint32_t)khA * 16) ^ swzA);
                    ldsm_x4(a[0], aA + ka);
                    ldsm_x4(a[1], aA + 16 * 128 + ka);
                }
                if (ks < 3) {
                    const int nxt = cur ^ 1;
                    uint32_t kb = (((uint32_t)(ks + 1) * 32 + (uint32_t)khB * 16) ^ swzB);
                    #pragma unroll
                    for (int nb = 0; nb < 4; ++nb)
                        ldsm_x4(b[nxt][nb], aB + (uint32_t)(nb * 16) * 128 + kb);
                }
                #pragma unroll
                for (int mi = 0; mi < 2; ++mi)
                    #pragma unroll
                    for (int ni = 0; ni < 8; ++ni)
                        mma16816(acc[mi][ni], a[mi],
                                 b[cur][ni >> 1][(ni & 1) * 2],
                                 b[cur][ni >> 1][(ni & 1) * 2 + 1]);
            }
            __syncthreads();
        }

        // ---- stats from registers: per-column sum/sumsq over this 128-row tile ----
        float csum[8][2], csq[8][2];
        #pragma unroll
        for (int ni = 0; ni < 8; ++ni) {
            #pragma unroll
            for (int q = 0; q < 2; ++q) {
                float a0v = acc[0][ni][q],    a1 = acc[0][ni][q + 2];
                float a2  = acc[1][ni][q],    a3 = acc[1][ni][q + 2];
                csum[ni][q] = (a0v + a1) + (a2 + a3);
                csq [ni][q] = fmaf(a0v, a0v, fmaf(a1, a1, fmaf(a2, a2, a3 * a3)));
            }
        }
        #pragma unroll
        for (int m = 4; m <= 16; m <<= 1) {
            #pragma unroll
            for (int ni = 0; ni < 8; ++ni) {
                #pragma unroll
                for (int q = 0; q < 2; ++q) {
                    csum[ni][q] += __shfl_xor_sync(0xFFFFFFFFu, csum[ni][q], m);
                    csq [ni][q] += __shfl_xor_sync(0xFFFFFFFFu, csq [ni][q], m);
                }
            }
        }
        float* s_sum = reinterpret_cast<float*>(sptr);          // [4][128]
        float* s_sq  = s_sum + 512;                              // [4][128]
        if ((lane >> 2) == 0) {
            int cbase = warp_n * 64 + (lane & 3) * 2;
            #pragma unroll
            for (int ni = 0; ni < 8; ++ni) {
                #pragma unroll
                for (int q = 0; q < 2; ++q) {
                    s_sum[warp_m * 128 + cbase + ni * 8 + q] = csum[ni][q];
                    s_sq [warp_m * 128 + cbase + ni * 8 + q] = csq [ni][q];
                }
            }
        }
        __syncthreads();
        if (tid < 128) {
            float ts = (s_sum[tid] + s_sum[128 + tid]) + (s_sum[256 + tid] + s_sum[384 + tid]);
            float tq = (s_sq [tid] + s_sq [128 + tid]) + (s_sq [256 + tid] + s_sq [384 + tid]);
            g_psum[mt * YCOLS + o * DOUT + tid] = ts;
            g_psq [mt * YCOLS + o * DOUT + tid] = tq;
        }
    }
    grid_barrier(1);

    // ================= phase 2 (LOCAL): finalize scale/shift for THIS CTA's 128 cols ====
    float* s_scale = reinterpret_cast<float*>(sptr);          // [128]
    float* s_shift = s_scale + 128;                            // [128]
    if (tid < 128) {
        int j = o * DOUT + tid;
        float sum = 0.f, sq = 0.f;
        #pragma unroll
        for (int s = 0; s < NMT; ++s) {
            sum += g_psum[s * YCOLS + j];
            sq  += g_psq [s * YCOLS + j];
        }
        float inv = 1.0f / (float)B_DIM;
        float mean = sum * inv;
        float var  = fmaf(sq, inv, -mean * mean);
        float sc = gamma[j] * rsqrtf(var + BN_EPS);
        s_scale[tid] = sc;
        s_shift[tid] = fmaf(-mean, sc, beta[j]);
    }
    __syncthreads();

    // ================= phase 3: BN + SiLU on the register tile -> out (streaming) ======
    {
        const int r0 = mt * 128 + warp_m * 32 + (lane >> 2);
        const int lc0 = warp_n * 64 + (lane & 3) * 2;          // local col in [0,128)
        const int col0 = o * DOUT + lc0;
        #pragma unroll
        for (int ni = 0; ni < 8; ++ni) {
            float2 sc = *reinterpret_cast<const float2*>(s_scale + lc0 + ni * 8);
            float2 sh = *reinterpret_cast<const float2*>(s_shift + lc0 + ni * 8);
            #pragma unroll
            for (int mi = 0; mi < 2; ++mi) {
                float y0 = fmaf(acc[mi][ni][0], sc.x, sh.x);
                float y1 = fmaf(acc[mi][ni][1], sc.y, sh.y);
                float y2 = fmaf(acc[mi][ni][2], sc.x, sh.x);
                float y3 = fmaf(acc[mi][ni][3], sc.y, sh.y);
                float2 r0v, r1v;
                r0v.x = y0 * rcp_fast(1.0f + __expf(-y0));
                r0v.y = y1 * rcp_fast(1.0f + __expf(-y1));
                r1v.x = y2 * rcp_fast(1.0f + __expf(-y2));
                r1v.y = y3 * rcp_fast(1.0f + __expf(-y3));
                float* p0 = out + (size_t)(r0 + mi * 16) * YCOLS + col0 + ni * 8;
                stg_cs_f2(p0, r0v);
                stg_cs_f2(p0 + 8 * YCOLS, r1v);
            }
        }
    }
}

// ---------------- launch ----------------
extern "C" void kernel_launch(void* const* d_in, const int* in_sizes, int n_in,
                              void* d_out, int out_size) {
    const float* x     = (const float*)d_in[0];   // (512,64,128)
    const float* W     = (const float*)d_in[1];   // (64,4,128,128)
    // d_in[2] = bias: provably cancelled by BatchNorm (batch-constant shift) — unused.
    const float* gamma = (const float*)d_in[3];   // (8192)
    const float* beta  = (const float*)d_in[4];   // (8192)
    const int*   idx   = (const int*)d_in[5];     // (64,4)
    float* out = (float*)d_out;

    cudaFuncSetAttribute(eb_mega, cudaFuncAttributeMaxDynamicSharedMemorySize, GEMM_SMEM_BYTES);
    eb_mega<<<NCTA, 256, GEMM_SMEM_BYTES>>>(x, W, gamma, beta, idx, out);
}

// round 16
// speedup vs baseline: 1.0070x; 1.0070x over previous
#include <cuda_runtime.h>
#include <cuda_fp16.h>
#include <cstdint>

// ---------------- problem dims ----------------
#define B_DIM 512
#define NIN   64
#define DIN   128
#define NOUT  64
#define DOUT  128
#define KSEL  4
#define YCOLS (NOUT * DOUT)        // 8192
#define BN_EPS 1e-5f

#define KD      (KSEL * DIN)       // 512 (logical K per head)
#define NCHUNK  8                  // 4 k-sel x 2 half-DIN; 64 fp16 per chunk
#define NMT     4                  // M-tiles per head (partial-stats slots)
#define NCTA    256                // all co-resident: 2/SM x 148 SMs = 296 slots

// ---------------- scratch (device globals; no allocation allowed) ----------------
__device__ __align__(16) __half  g_xh[B_DIM * NIN * DIN];     // 8.4 MB
__device__ __align__(16) __half  g_wt[NOUT * DOUT * KD];      // [o][e][k*128+d], 8.4 MB
__device__ __align__(16) float   g_psum[NMT * YCOLS];         // 128 KB
__device__ __align__(16) float   g_psq [NMT * YCOLS];         // 128 KB
__device__ unsigned int          g_bar[4];                    // global ticket barrier
__device__ unsigned int          g_hbar[NOUT];                // per-head ticket barriers

// ---------------- helpers ----------------
__device__ __forceinline__ uint32_t smem_u32(const void* p) {
    uint32_t a;
    asm("{ .reg .u64 t; cvta.to.shared.u64 t, %1; cvt.u32.u64 %0, t; }" : "=r"(a) : "l"(p));
    return a;
}
__device__ __forceinline__ void cp_async16(uint32_t dst, const void* src) {
    asm volatile("cp.async.cg.shared.global [%0], [%1], 16;" :: "r"(dst), "l"(src) : "memory");
}
__device__ __forceinline__ void cp_commit() {
    asm volatile("cp.async.commit_group;" ::: "memory");
}
template <int N>
__device__ __forceinline__ void cp_wait() {
    asm volatile("cp.async.wait_group %0;" :: "n"(N) : "memory");
}
__device__ __forceinline__ void ldsm_x4(uint32_t* r, uint32_t addr) {
    asm volatile("ldmatrix.sync.aligned.m8n8.x4.shared.b16 {%0,%1,%2,%3}, [%4];"
                 : "=r"(r[0]), "=r"(r[1]), "=r"(r[2]), "=r"(r[3]) : "r"(addr));
}
__device__ __forceinline__ void mma16816(float* d, const uint32_t* a, uint32_t b0, uint32_t b1) {
    asm volatile(
        "mma.sync.aligned.m16n8k16.row.col.f32.f16.f16.f32 "
        "{%0,%1,%2,%3}, {%4,%5,%6,%7}, {%8,%9}, {%0,%1,%2,%3};"
        : "+f"(d[0]), "+f"(d[1]), "+f"(d[2]), "+f"(d[3])
        : "r"(a[0]), "r"(a[1]), "r"(a[2]), "r"(a[3]), "r"(b0), "r"(b1));
}
__device__ __forceinline__ float rcp_fast(float x) {
    float r;
    asm("rcp.approx.f32 %0, %1;" : "=f"(r) : "f"(x));
    return r;
}
__device__ __forceinline__ void stg_cs_f2(float* p, float2 v) {
    asm volatile("st.global.cs.v2.f32 [%0], {%1, %2};" :: "l"(p), "f"(v.x), "f"(v.y) : "memory");
}

// Grid-wide barrier: monotonic ticket counter, no reset needed (replay-safe).
__device__ __forceinline__ void grid_barrier(int slot) {
    __syncthreads();
    if (threadIdx.x == 0) {
        __threadfence();
        unsigned ticket = atomicAdd(&g_bar[slot], 1u);
        unsigned target = (ticket / NCTA + 1u) * NCTA;
        unsigned v;
        do {
            asm volatile("ld.acquire.gpu.u32 %0, [%1];"
                         : "=r"(v) : "l"(&g_bar[slot]));
        } while ((int)(v - target) < 0);
    }
    __syncthreads();
}

// Per-head barrier: only the 4 CTAs of head o synchronize (same monotonic
// ticket scheme). BN stats for head o depend ONLY on these 4 CTAs, so a
// global barrier over-synchronizes 64x; this lets early heads run their
// MUFU-heavy epilogue while straggler heads are still in the MMA mainloop.
__device__ __forceinline__ void head_barrier(int o) {
    __syncthreads();
    if (threadIdx.x == 0) {
        __threadfence();
        unsigned ticket = atomicAdd(&g_hbar[o], 1u);
        unsigned target = (ticket / NMT + 1u) * NMT;
        unsigned v;
        do {
            asm volatile("ld.acquire.gpu.u32 %0, [%1];"
                         : "=r"(v) : "l"(&g_hbar[o]));
        } while ((int)(v - target) < 0);
    }
    __syncthreads();
}

// ---------------- THE mega kernel ----------------
#define STAGE_BYTES 32768
#define GEMM_SMEM_BYTES (3 * STAGE_BYTES + 1024)

__global__ void __launch_bounds__(256, 2)
eb_mega(const float* __restrict__ x, const float* __restrict__ W,
        const float* __restrict__ gamma, const float* __restrict__ beta,
        const int* __restrict__ idx, float* __restrict__ out) {
    extern __shared__ char dsm[];
    uint32_t raw = smem_u32(dsm);
    uint32_t sbase = (raw + 1023u) & ~1023u;
    char* sptr = dsm + (sbase - raw);

    const int tid  = threadIdx.x;
    const int bid  = blockIdx.x;

    // ================= phase 0: convert inputs =================
    {
        const float4* xin = reinterpret_cast<const float4*>(x);
        #pragma unroll
        for (int it = 0; it < 16; ++it) {
            int i = bid * 4096 + it * 256 + tid;
            float4 v = xin[i];
            __half2 p0 = __floats2half2_rn(v.x, v.y);
            __half2 p1 = __floats2half2_rn(v.z, v.w);
            uint2 pk;
            pk.x = *reinterpret_cast<uint32_t*>(&p0);
            pk.y = *reinterpret_cast<uint32_t*>(&p1);
            reinterpret_cast<uint2*>(g_xh)[i] = pk;
        }
        float* tile = reinterpret_cast<float*>(sptr);   // [128][33]
        int o = bid >> 2, k = bid & 3;
        const float4* src4 = reinterpret_cast<const float4*>(W + (size_t)bid * (DIN * DOUT));
        for (int eb = 0; eb < 4; ++eb) {
            __syncthreads();
            #pragma unroll
            for (int it = 0; it < 4; ++it) {
                int flat = it * 256 + tid;          // 0..1023
                int d = flat >> 3, e4 = flat & 7;
                float4 v = src4[d * (DOUT / 4) + eb * 8 + e4];
                float* trow = tile + d * 33 + e4 * 4;
                trow[0] = v.x; trow[1] = v.y; trow[2] = v.z; trow[3] = v.w;
            }
            __syncthreads();
            #pragma unroll
            for (int it = 0; it < 16; ++it) {
                int flat = it * 256 + tid;
                int e2 = flat >> 7, d = flat & 127;
                float v = tile[d * 33 + e2];
                size_t off = (size_t)o * (DOUT * KD) + (size_t)(eb * 32 + e2) * KD + k * DIN + d;
                g_wt[off] = __float2half_rn(v);
            }
        }
    }
    grid_barrier(0);

    // ================= phase 1: GEMM + stats (accumulators stay live) =================
    const int lane = tid & 31;
    const int wid  = tid >> 5;
    const int warp_m = wid & 3;          // 4 M-warps of 32 rows
    const int warp_n = wid >> 2;         // 2 N-warps of 64 cols
    const int o  = bid >> 2;
    const int mt = bid & 3;

    float acc[2][8][4];
    #pragma unroll
    for (int mi = 0; mi < 2; ++mi)
        #pragma unroll
        for (int ni = 0; ni < 8; ++ni)
            #pragma unroll
            for (int q = 0; q < 4; ++q) acc[mi][ni][q] = 0.0f;

    {
        int nin[4];
        #pragma unroll
        for (int k = 0; k < 4; ++k) nin[k] = idx[(o << 2) + k];

        auto prefetch = [&](int c) {
            int k = c >> 1, dh = c & 1;
            uint32_t abuf = sbase + (uint32_t)(c % 3) * STAGE_BYTES;
            uint32_t bbuf = abuf + 16384;
            const __half* abase = g_xh + ((size_t)(mt * 128) * NIN + nin[k]) * DIN + dh * 64;
            const __half* bbase = g_wt + (size_t)o * (DOUT * KD) + k * DIN + dh * 64;
            #pragma unroll
            for (int it = 0; it < 4; ++it) {
                int v = it * 256 + tid;          // 1024 16B chunks per tile
                int row = v >> 3, cc = v & 7;
                uint32_t dsw = (uint32_t)row * 128 + (((uint32_t)cc * 16) ^ (((uint32_t)row & 7) << 4));
                cp_async16(abuf + dsw, abase + (size_t)row * (NIN * DIN) + cc * 8);
                cp_async16(bbuf + dsw, bbase + (size_t)row * KD + cc * 8);
            }
        };

        const int sub = lane >> 3;
        const int rowA = warp_m * 32 + (sub & 1) * 8 + (lane & 7);
        const int khA  = sub >> 1;
        const uint32_t swzA = ((uint32_t)rowA & 7) << 4;
        const int rowB = warp_n * 64 + (sub >> 1) * 8 + (lane & 7);
        const int khB  = sub & 1;
        const uint32_t swzB = ((uint32_t)rowB & 7) << 4;

        prefetch(0); cp_commit();
        prefetch(1); cp_commit();

        for (int c = 0; c < NCHUNK; ++c) {
            cp_wait<1>();
            __syncthreads();
            if (c + 2 < NCHUNK) prefetch(c + 2);
            cp_commit();

            uint32_t abuf = sbase + (uint32_t)(c % 3) * STAGE_BYTES;
            uint32_t bbuf = abuf + 16384;
            uint32_t aA  = abuf + (uint32_t)rowA * 128;
            uint32_t aB  = bbuf + (uint32_t)rowB * 128;

            // B fragments double-buffered across ks (hides LDSM latency)
            uint32_t b[2][4][4];
            {
                uint32_t kb0 = ((uint32_t)khB * 16) ^ swzB;
                #pragma unroll
                for (int nb = 0; nb < 4; ++nb)
                    ldsm_x4(b[0][nb], aB + (uint32_t)(nb * 16) * 128 + kb0);
            }
            #pragma unroll
            for (int ks = 0; ks < 4; ++ks) {
                const int cur = ks & 1;
                uint32_t ka = (((uint32_t)ks * 32 + (uint32_t)khA * 16) ^ swzA);
                uint32_t a[2][4];
                ldsm_x4(a[0], aA + ka);
                ldsm_x4(a[1], aA + 16 * 128 + ka);
                if (ks < 3) {
                    const int nxt = cur ^ 1;
                    uint32_t kb = (((uint32_t)(ks + 1) * 32 + (uint32_t)khB * 16) ^ swzB);
                    #pragma unroll
                    for (int nb = 0; nb < 4; ++nb)
                        ldsm_x4(b[nxt][nb], aB + (uint32_t)(nb * 16) * 128 + kb);
                }
                #pragma unroll
                for (int mi = 0; mi < 2; ++mi)
                    #pragma unroll
                    for (int ni = 0; ni < 8; ++ni)
                        mma16816(acc[mi][ni], a[mi],
                                 b[cur][ni >> 1][(ni & 1) * 2],
                                 b[cur][ni >> 1][(ni & 1) * 2 + 1]);
            }
            __syncthreads();
        }

        // ---- stats from registers: per-column sum/sumsq over this 128-row tile ----
        float csum[8][2], csq[8][2];
        #pragma unroll
        for (int ni = 0; ni < 8; ++ni) {
            #pragma unroll
            for (int q = 0; q < 2; ++q) {
                float a0 = acc[0][ni][q],     a1 = acc[0][ni][q + 2];
                float a2 = acc[1][ni][q],     a3 = acc[1][ni][q + 2];
                csum[ni][q] = (a0 + a1) + (a2 + a3);
                csq [ni][q] = fmaf(a0, a0, fmaf(a1, a1, fmaf(a2, a2, a3 * a3)));
            }
        }
        #pragma unroll
        for (int m = 4; m <= 16; m <<= 1) {
            #pragma unroll
            for (int ni = 0; ni < 8; ++ni) {
                #pragma unroll
                for (int q = 0; q < 2; ++q) {
                    csum[ni][q] += __shfl_xor_sync(0xFFFFFFFFu, csum[ni][q], m);
                    csq [ni][q] += __shfl_xor_sync(0xFFFFFFFFu, csq [ni][q], m);
                }
            }
        }
        float* s_sum = reinterpret_cast<float*>(sptr);          // [4][128]
        float* s_sq  = s_sum + 512;                              // [4][128]
        if ((lane >> 2) == 0) {
            int cbase = warp_n * 64 + (lane & 3) * 2;
            #pragma unroll
            for (int ni = 0; ni < 8; ++ni) {
                #pragma unroll
                for (int q = 0; q < 2; ++q) {
                    s_sum[warp_m * 128 + cbase + ni * 8 + q] = csum[ni][q];
                    s_sq [warp_m * 128 + cbase + ni * 8 + q] = csq [ni][q];
                }
            }
        }
        __syncthreads();
        if (tid < 128) {
            float ts = (s_sum[tid] + s_sum[128 + tid]) + (s_sum[256 + tid] + s_sum[384 + tid]);
            float tq = (s_sq [tid] + s_sq [128 + tid]) + (s_sq [256 + tid] + s_sq [384 + tid]);
            g_psum[mt * YCOLS + o * DOUT + tid] = ts;
            g_psq [mt * YCOLS + o * DOUT + tid] = tq;
        }
    }
    // Only the 4 CTAs of this head need to rendezvous (BN stats are per-head).
    head_barrier(o);

    // ================= phase 2 (LOCAL): finalize scale/shift for THIS CTA's 128 cols ====
    float* s_scale = reinterpret_cast<float*>(sptr);          // [128]
    float* s_shift = s_scale + 128;                            // [128]
    if (tid < 128) {
        int j = o * DOUT + tid;
        float sum = 0.f, sq = 0.f;
        #pragma unroll
        for (int s = 0; s < NMT; ++s) {
            sum += g_psum[s * YCOLS + j];
            sq  += g_psq [s * YCOLS + j];
        }
        float inv = 1.0f / (float)B_DIM;
        float mean = sum * inv;
        float var  = fmaf(sq, inv, -mean * mean);
        float sc = gamma[j] * rsqrtf(var + BN_EPS);
        s_scale[tid] = sc;
        s_shift[tid] = fmaf(-mean, sc, beta[j]);
    }
    __syncthreads();

    // ================= phase 3: BN + SiLU on the register tile -> out (streaming) ======
    {
        const int r0 = mt * 128 + warp_m * 32 + (lane >> 2);
        const int lc0 = warp_n * 64 + (lane & 3) * 2;          // local col in [0,128)
        const int col0 = o * DOUT + lc0;
        #pragma unroll
        for (int ni = 0; ni < 8; ++ni) {
            float2 sc = *reinterpret_cast<const float2*>(s_scale + lc0 + ni * 8);
            float2 sh = *reinterpret_cast<const float2*>(s_shift + lc0 + ni * 8);
            #pragma unroll
            for (int mi = 0; mi < 2; ++mi) {
                float y0 = fmaf(acc[mi][ni][0], sc.x, sh.x);
                float y1 = fmaf(acc[mi][ni][1], sc.y, sh.y);
                float y2 = fmaf(acc[mi][ni][2], sc.x, sh.x);
                float y3 = fmaf(acc[mi][ni][3], sc.y, sh.y);
                float2 r0v, r1v;
                r0v.x = y0 * rcp_fast(1.0f + __expf(-y0));
                r0v.y = y1 * rcp_fast(1.0f + __expf(-y1));
                r1v.x = y2 * rcp_fast(1.0f + __expf(-y2));
                r1v.y = y3 * rcp_fast(1.0f + __expf(-y3));
                float* p0 = out + (size_t)(r0 + mi * 16) * YCOLS + col0 + ni * 8;
                stg_cs_f2(p0, r0v);
                stg_cs_f2(p0 + 8 * YCOLS, r1v);
            }
        }
    }
}

// ---------------- launch ----------------
extern "C" void kernel_launch(void* const* d_in, const int* in_sizes, int n_in,
                              void* d_out, int out_size) {
    const float* x     = (const float*)d_in[0];   // (512,64,128)
    const float* W     = (const float*)d_in[1];   // (64,4,128,128)
    // d_in[2] = bias: provably cancelled by BatchNorm (batch-constant shift) — unused.
    const float* gamma = (const float*)d_in[3];   // (8192)
    const float* beta  = (const float*)d_in[4];   // (8192)
    const int*   idx   = (const int*)d_in[5];     // (64,4)
    float* out = (float*)d_out;

    cudaFuncSetAttribute(eb_mega, cudaFuncAttributeMaxDynamicSharedMemorySize, GEMM_SMEM_BYTES);
    eb_mega<<<NCTA, 256, GEMM_SMEM_BYTES>>>(x, W, gamma, beta, idx, out);
}